// round 16
// baseline (speedup 1.0000x reference)
#include <cuda_runtime.h>
#include <cuda_bf16.h>
#include <math.h>

// Problem constants
#define BATCH 128
#define TIN   2048
#define TO    2047   // conv 'valid' output length
#define FCH   64     // conv filters
#define HID   100    // LSTM units
#define G4    400    // 4*HID
#define NA    3      // actions

// ---------------------------------------------------------------------------
// Packed f32x2 helpers (sm_103a FFMA2 path)
// ---------------------------------------------------------------------------
__device__ __forceinline__ unsigned long long pack2(float lo, float hi) {
    unsigned long long r;
    asm("mov.b64 %0, {%1, %2};" : "=l"(r) : "f"(lo), "f"(hi));
    return r;
}
__device__ __forceinline__ void unpack2(unsigned long long v, float& lo, float& hi) {
    asm("mov.b64 {%0, %1}, %2;" : "=f"(lo), "=f"(hi) : "l"(v));
}
__device__ __forceinline__ unsigned long long ffma2(unsigned long long a,
                                                    unsigned long long b,
                                                    unsigned long long c) {
    unsigned long long d;
    asm("fma.rn.f32x2 %0, %1, %2, %3;" : "=l"(d) : "l"(a), "l"(b), "l"(c));
    return d;
}

// ---------------------------------------------------------------------------
// Scratch (device globals; no allocation allowed)
// ---------------------------------------------------------------------------
__device__ float g_xz1[(size_t)BATCH * TO * G4];   // ~419 MB
__device__ float g_h1 [(size_t)BATCH * TO * HID];  // ~105 MB
__device__ float g_xz2[(size_t)BATCH * TO * G4];   // ~419 MB
__device__ float g_h2 [BATCH * HID];

// ---------------------------------------------------------------------------
// Kernel A (exact R14): conv1d(k=2)+relu fused with x @ W1 + b1 -> g_xz1
// Full-width tile 64t x 400g, K=64, 400 threads, 8t x 8g register block.
// ---------------------------------------------------------------------------
__global__ void __launch_bounds__(400, 1)
conv_xz1_kernel(const float* __restrict__ s,
                const float* __restrict__ cw,
                const float* __restrict__ cb,
                const float* __restrict__ W1,
                const float* __restrict__ b1) {
    extern __shared__ __align__(16) float sm[];
    float* s_s = sm;                                       // [68]
    float(*x_s)[64]  = (float(*)[64])(sm + 68);            // [64][64]
    float(*w_s)[G4]  = (float(*)[G4])(sm + 68 + 64 * 64);  // [64][400]

    const int b  = blockIdx.z;
    const int t0 = blockIdx.x * 64;
    const int tid = threadIdx.x;

    for (int i = tid; i < 65; i += 400) {
        int t = t0 + i;
        s_s[i] = (t < TIN) ? s[(size_t)b * TIN + t] : 0.f;
    }
    __syncthreads();

    // conv+relu tile: x[f][tt]
    for (int i = tid; i < 64 * 64; i += 400) {
        int f = i >> 6, tt = i & 63;
        float v = fmaf(s_s[tt], cw[f], fmaf(s_s[tt + 1], cw[64 + f], cb[f]));
        x_s[f][tt] = fmaxf(v, 0.f);
    }
    // W1 full width: linear float4 copy (64*400 floats)
    {
        const float4* Wv = (const float4*)W1;
        float4* wv = (float4*)w_s;
#pragma unroll
        for (int i = tid; i < 64 * 100; i += 400) wv[i] = Wv[i];
    }
    __syncthreads();

    const int gy = tid % 50;   // 8-g group
    const int tx = tid / 50;   // 8-t group
    unsigned long long acc2[8][4] = {};
#pragma unroll
    for (int k = 0; k < 64; k++) {
        float4 xa0 = *(const float4*)&x_s[k][tx * 8];
        float4 xa1 = *(const float4*)&x_s[k][tx * 8 + 4];
        ulonglong2 wA = *(const ulonglong2*)&w_s[k][gy * 8];
        ulonglong2 wB = *(const ulonglong2*)&w_s[k][gy * 8 + 4];
        float xv[8] = {xa0.x, xa0.y, xa0.z, xa0.w, xa1.x, xa1.y, xa1.z, xa1.w};
#pragma unroll
        for (int ti = 0; ti < 8; ti++) {
            unsigned long long xx = pack2(xv[ti], xv[ti]);
            acc2[ti][0] = ffma2(xx, wA.x, acc2[ti][0]);
            acc2[ti][1] = ffma2(xx, wA.y, acc2[ti][1]);
            acc2[ti][2] = ffma2(xx, wB.x, acc2[ti][2]);
            acc2[ti][3] = ffma2(xx, wB.y, acc2[ti][3]);
        }
    }

    const int g8 = gy * 8;
    float4 bv0 = *(const float4*)&b1[g8];
    float4 bv1 = *(const float4*)&b1[g8 + 4];
#pragma unroll
    for (int ti = 0; ti < 8; ti++) {
        int t = t0 + tx * 8 + ti;
        if (t >= TO) continue;
        float4 v0, v1;
        unpack2(acc2[ti][0], v0.x, v0.y);
        unpack2(acc2[ti][1], v0.z, v0.w);
        unpack2(acc2[ti][2], v1.x, v1.y);
        unpack2(acc2[ti][3], v1.z, v1.w);
        v0.x += bv0.x; v0.y += bv0.y; v0.z += bv0.z; v0.w += bv0.w;
        v1.x += bv1.x; v1.y += bv1.y; v1.z += bv1.z; v1.w += bv1.w;
        float* dst = &g_xz1[((size_t)b * TO + t) * G4 + g8];
        *(float4*)dst = v0;
        *(float4*)(dst + 4) = v1;
    }
}

// ---------------------------------------------------------------------------
// Kernel C (exact R14): xz2 = h1seq @ W2 + b2 -> g_xz2 [B,TO,400]  (K = 100)
// Full-width tile 64t x 400g, 400 threads, 8t x 8g register block.
// ---------------------------------------------------------------------------
#define XS_PAD 68
__global__ void __launch_bounds__(400, 1)
proj2_kernel(const float* __restrict__ W2,
             const float* __restrict__ b2) {
    extern __shared__ __align__(16) float sm[];
    float(*x_s)[XS_PAD] = (float(*)[XS_PAD])sm;               // [100][68]
    float(*w_s)[G4]     = (float(*)[G4])(sm + 100 * XS_PAD);  // [100][400]

    const int b  = blockIdx.z;
    const int t0 = blockIdx.x * 64;
    const int tid = threadIdx.x;

    // load h1 tile [64 t][100 k], transposed into x_s[k][tt] (coalesced LDG)
    for (int i = tid; i < 64 * HID; i += 400) {
        int tt = i / HID, k = i % HID;
        int t = t0 + tt;
        x_s[k][tt] = (t < TO) ? g_h1[((size_t)b * TO + t) * HID + k] : 0.f;
    }
    // W2 full width: linear float4 copy (100*400 floats)
    {
        const float4* Wv = (const float4*)W2;
        float4* wv = (float4*)w_s;
#pragma unroll
        for (int i = tid; i < 100 * 100; i += 400) wv[i] = Wv[i];
    }
    __syncthreads();

    const int gy = tid % 50;
    const int tx = tid / 50;
    unsigned long long acc2[8][4] = {};
#pragma unroll 4
    for (int k = 0; k < HID; k++) {
        float4 xa0 = *(const float4*)&x_s[k][tx * 8];
        float4 xa1 = *(const float4*)&x_s[k][tx * 8 + 4];
        ulonglong2 wA = *(const ulonglong2*)&w_s[k][gy * 8];
        ulonglong2 wB = *(const ulonglong2*)&w_s[k][gy * 8 + 4];
        float xv[8] = {xa0.x, xa0.y, xa0.z, xa0.w, xa1.x, xa1.y, xa1.z, xa1.w};
#pragma unroll
        for (int ti = 0; ti < 8; ti++) {
            unsigned long long xx = pack2(xv[ti], xv[ti]);
            acc2[ti][0] = ffma2(xx, wA.x, acc2[ti][0]);
            acc2[ti][1] = ffma2(xx, wA.y, acc2[ti][1]);
            acc2[ti][2] = ffma2(xx, wB.x, acc2[ti][2]);
            acc2[ti][3] = ffma2(xx, wB.y, acc2[ti][3]);
        }
    }

    const int g8 = gy * 8;
    float4 bv0 = *(const float4*)&b2[g8];
    float4 bv1 = *(const float4*)&b2[g8 + 4];
#pragma unroll
    for (int ti = 0; ti < 8; ti++) {
        int t = t0 + tx * 8 + ti;
        if (t >= TO) continue;
        float4 v0, v1;
        unpack2(acc2[ti][0], v0.x, v0.y);
        unpack2(acc2[ti][1], v0.z, v0.w);
        unpack2(acc2[ti][2], v1.x, v1.y);
        unpack2(acc2[ti][3], v1.z, v1.w);
        v0.x += bv0.x; v0.y += bv0.y; v0.z += bv0.z; v0.w += bv0.w;
        v1.x += bv1.x; v1.y += bv1.y; v1.z += bv1.z; v1.w += bv1.w;
        float* dst = &g_xz2[((size_t)b * TO + t) * G4 + g8];
        *(float4*)dst = v0;
        *(float4*)(dst + 4) = v1;
    }
}

// ---------------------------------------------------------------------------
// Scan kernel: R7/R14 structure, but xz prefetch pipeline DEEPENED to
// distance 3 (3 LDGs in flight via __ldcg) to break the MLP=1 DRAM-latency
// bound: step t consumes xz[t] loaded 3 steps earlier; each step issues
// the load for t+3. Everything else identical to the 4616us baseline.
// ---------------------------------------------------------------------------
__global__ void __launch_bounds__(400, 1)
lstm_scan_kernel(const float* __restrict__ xz,
                 const float* __restrict__ U,
                 float* __restrict__ hseq,
                 int seq) {
    __shared__ __align__(16) float h_s[2][104];

    const int b = blockIdx.x;
    const int tid = threadIdx.x;
    const int j   = tid >> 2;
    const int sub = tid & 3;
    const int g   = sub * 100 + j;          // column in z-space
    const int lane = tid & 31;
    const unsigned mask = (tid < 384) ? 0xFFFFFFFFu : 0x0000FFFFu;

    // U column packed in k-pairs: Ur2[k2] = (U[2k2, g], U[2k2+1, g])
    unsigned long long Ur2[50];
#pragma unroll
    for (int k2 = 0; k2 < 50; k2++)
        Ur2[k2] = pack2(U[(2 * k2) * G4 + g], U[(2 * k2 + 1) * G4 + g]);

    float c = 0.f;
    if (tid < 104) { h_s[0][tid] = 0.f; h_s[1][tid] = 0.f; }
    __syncthreads();

    const float* xzb = xz + (size_t)b * TO * G4;
    // prefetch pipeline, distance 3: slots for t, t+1, t+2
    float xz_p0 = __ldcg(&xzb[g]);                              // t = 0
    float xz_p1 = __ldcg(&xzb[(size_t)1 * G4 + g]);             // t = 1
    float xz_p2 = __ldcg(&xzb[(size_t)2 * G4 + g]);             // t = 2
    int cur = 0;

    for (int t = 0; t < TO; t++) {
        // issue load for t+3 (clamped); 3 loads always in flight
        int tn = (t + 3 < TO) ? (t + 3) : (TO - 1);
        float xz_p3 = __ldcg(&xzb[(size_t)tn * G4 + g]);

        const ulonglong2* hp = (const ulonglong2*)h_s[cur];
        unsigned long long aA = 0ULL;   // packed (k%4==0 sum, k%4==1 sum)
        unsigned long long aB = 0ULL;   // packed (k%4==2 sum, k%4==3 sum)
#pragma unroll
        for (int k2 = 0; k2 < 25; k2++) {
            ulonglong2 hv = hp[k2];     // 4 h values (16B)
            aA = ffma2(hv.x, Ur2[2 * k2],     aA);
            aB = ffma2(hv.y, Ur2[2 * k2 + 1], aB);
        }
        float a0, a1, a2, a3;
        unpack2(aA, a0, a1);
        unpack2(aB, a2, a3);
        float z = (a0 + a1) + (a2 + a3) + xz_p0;

        // per-lane activation, then nibble gather of activated gate values
        float sg = 1.f / (1.f + __expf(-z));
        float act = (sub == 2) ? fmaxf(z, 0.f) : sg;
        const int base = lane & ~3;
        float ig = __shfl_sync(mask, act, base + 0);
        float fg = __shfl_sync(mask, act, base + 1);
        float gc = __shfl_sync(mask, act, base + 2);
        float og = __shfl_sync(mask, act, base + 3);

        c = fmaf(fg, c, ig * gc);
        float h = og * fmaxf(c, 0.f);

        if (sub == 0) {
            h_s[cur ^ 1][j] = h;
            if (seq) {
                hseq[((size_t)b * TO + t) * HID + j] = h;
            } else if (t == TO - 1) {
                g_h2[b * HID + j] = h;
            }
        }
        __syncthreads();   // h published; all reads of h_s[cur] complete
        cur ^= 1;
        // rotate prefetch pipeline
        xz_p0 = xz_p1;
        xz_p1 = xz_p2;
        xz_p2 = xz_p3;
    }
}

// ---------------------------------------------------------------------------
// Kernel E: dense + softmax. One warp per batch row.
// ---------------------------------------------------------------------------
__global__ void dense_softmax_kernel(const float* __restrict__ dw,
                                     const float* __restrict__ db,
                                     float* __restrict__ out) {
    const int b = blockIdx.x;
    const int lane = threadIdx.x;
    float p0 = 0.f, p1 = 0.f, p2 = 0.f;
    for (int j = lane; j < HID; j += 32) {
        float h = g_h2[b * HID + j];
        p0 = fmaf(h, dw[j * 3 + 0], p0);
        p1 = fmaf(h, dw[j * 3 + 1], p1);
        p2 = fmaf(h, dw[j * 3 + 2], p2);
    }
#pragma unroll
    for (int o = 16; o; o >>= 1) {
        p0 += __shfl_down_sync(0xffffffffu, p0, o);
        p1 += __shfl_down_sync(0xffffffffu, p1, o);
        p2 += __shfl_down_sync(0xffffffffu, p2, o);
    }
    if (lane == 0) {
        float l0 = p0 + db[0], l1 = p1 + db[1], l2 = p2 + db[2];
        float m = fmaxf(l0, fmaxf(l1, l2));
        float e0 = __expf(l0 - m), e1 = __expf(l1 - m), e2 = __expf(l2 - m);
        float inv = 1.f / (e0 + e1 + e2);
        out[b * 3 + 0] = e0 * inv;
        out[b * 3 + 1] = e1 * inv;
        out[b * 3 + 2] = e2 * inv;
    }
}

// ---------------------------------------------------------------------------
// Launch
// ---------------------------------------------------------------------------
extern "C" void kernel_launch(void* const* d_in, const int* in_sizes, int n_in,
                              void* d_out, int out_size) {
    const float* s       = (const float*)d_in[0];   // [128,2048,1]
    const float* conv_w  = (const float*)d_in[1];   // [2,1,64]
    const float* conv_b  = (const float*)d_in[2];   // [64]
    const float* lstm1_w = (const float*)d_in[3];   // [64,400]
    const float* lstm1_u = (const float*)d_in[4];   // [100,400]
    const float* lstm1_b = (const float*)d_in[5];   // [400]
    const float* lstm2_w = (const float*)d_in[6];   // [100,400]
    const float* lstm2_u = (const float*)d_in[7];   // [100,400]
    const float* lstm2_b = (const float*)d_in[8];   // [400]
    const float* dense_w = (const float*)d_in[9];   // [100,3]
    const float* dense_b = (const float*)d_in[10];  // [3]
    float* out = (float*)d_out;                     // [128,3]

    void* p_xz1; cudaGetSymbolAddress(&p_xz1, g_xz1);
    void* p_h1;  cudaGetSymbolAddress(&p_h1,  g_h1);
    void* p_xz2; cudaGetSymbolAddress(&p_xz2, g_xz2);

    // Phase A: conv + input projection for LSTM1 (full-width 8x8 tile)
    {
        int smem = (68 + 64 * 64 + 64 * G4) * sizeof(float);  // ~119 KB
        cudaFuncSetAttribute(conv_xz1_kernel,
                             cudaFuncAttributeMaxDynamicSharedMemorySize, smem);
        dim3 grid(32, 1, BATCH);
        conv_xz1_kernel<<<grid, 400, smem>>>(s, conv_w, conv_b, lstm1_w, lstm1_b);
    }
    // Phase B: LSTM1 scan (return sequences)
    lstm_scan_kernel<<<BATCH, 400>>>((const float*)p_xz1, lstm1_u,
                                     (float*)p_h1, 1);
    // Phase C: input projection for LSTM2 (full-width 8x8 tile)
    {
        int smem = (100 * XS_PAD + 100 * G4) * sizeof(float);  // ~187 KB
        cudaFuncSetAttribute(proj2_kernel,
                             cudaFuncAttributeMaxDynamicSharedMemorySize, smem);
        dim3 grid(32, 1, BATCH);
        proj2_kernel<<<grid, 400, smem>>>(lstm2_w, lstm2_b);
    }
    // Phase D: LSTM2 scan (last state only)
    lstm_scan_kernel<<<BATCH, 400>>>((const float*)p_xz2, lstm2_u,
                                     (float*)p_h1 /*unused*/, 0);
    // Phase E: dense + softmax
    dense_softmax_kernel<<<BATCH, 32>>>(dense_w, dense_b, out);
}

// round 17
// speedup vs baseline: 1.8365x; 1.8365x over previous
#include <cuda_runtime.h>
#include <cuda_bf16.h>
#include <math.h>

// Problem constants
#define BATCH 128
#define TIN   2048
#define TO    2047   // conv 'valid' output length
#define FCH   64     // conv filters
#define HID   100    // LSTM units
#define G4    400    // 4*HID
#define NA    3      // actions

#define NCHUNK 8
#define CHUNK  256   // ceil(2047/8) = 256; last chunk = 255

// ---------------------------------------------------------------------------
// Packed f32x2 helpers (sm_103a FFMA2 path)
// ---------------------------------------------------------------------------
__device__ __forceinline__ unsigned long long pack2(float lo, float hi) {
    unsigned long long r;
    asm("mov.b64 %0, {%1, %2};" : "=l"(r) : "f"(lo), "f"(hi));
    return r;
}
__device__ __forceinline__ void unpack2(unsigned long long v, float& lo, float& hi) {
    asm("mov.b64 {%0, %1}, %2;" : "=f"(lo), "=f"(hi) : "l"(v));
}
__device__ __forceinline__ unsigned long long ffma2(unsigned long long a,
                                                    unsigned long long b,
                                                    unsigned long long c) {
    unsigned long long d;
    asm("fma.rn.f32x2 %0, %1, %2, %3;" : "=l"(d) : "l"(a), "l"(b), "l"(c));
    return d;
}

// ---------------------------------------------------------------------------
// Scratch (device globals; no allocation allowed)
// ---------------------------------------------------------------------------
__device__ float g_xz1[(size_t)BATCH * TO * G4];   // ~419 MB
__device__ float g_h1 [(size_t)BATCH * TO * HID];  // ~105 MB
__device__ float g_xz2[(size_t)BATCH * TO * G4];   // ~419 MB
__device__ float g_h2 [BATCH * HID];               // scan2 h state (dense input)
__device__ float g_c1 [BATCH * HID];               // scan1 c state
__device__ float g_hs1[BATCH * HID];               // scan1 h state
__device__ float g_c2 [BATCH * HID];               // scan2 c state

// ---------------------------------------------------------------------------
// Kernel A (exact R14): conv1d(k=2)+relu fused with x @ W1 + b1 -> g_xz1
// Full-width tile 64t x 400g, K=64, 400 threads, 8t x 8g register block.
// ---------------------------------------------------------------------------
__global__ void __launch_bounds__(400, 1)
conv_xz1_kernel(const float* __restrict__ s,
                const float* __restrict__ cw,
                const float* __restrict__ cb,
                const float* __restrict__ W1,
                const float* __restrict__ b1) {
    extern __shared__ __align__(16) float sm[];
    float* s_s = sm;                                       // [68]
    float(*x_s)[64]  = (float(*)[64])(sm + 68);            // [64][64]
    float(*w_s)[G4]  = (float(*)[G4])(sm + 68 + 64 * 64);  // [64][400]

    const int b  = blockIdx.z;
    const int t0 = blockIdx.x * 64;
    const int tid = threadIdx.x;

    for (int i = tid; i < 65; i += 400) {
        int t = t0 + i;
        s_s[i] = (t < TIN) ? s[(size_t)b * TIN + t] : 0.f;
    }
    __syncthreads();

    for (int i = tid; i < 64 * 64; i += 400) {
        int f = i >> 6, tt = i & 63;
        float v = fmaf(s_s[tt], cw[f], fmaf(s_s[tt + 1], cw[64 + f], cb[f]));
        x_s[f][tt] = fmaxf(v, 0.f);
    }
    {
        const float4* Wv = (const float4*)W1;
        float4* wv = (float4*)w_s;
#pragma unroll
        for (int i = tid; i < 64 * 100; i += 400) wv[i] = Wv[i];
    }
    __syncthreads();

    const int gy = tid % 50;   // 8-g group
    const int tx = tid / 50;   // 8-t group
    unsigned long long acc2[8][4] = {};
#pragma unroll
    for (int k = 0; k < 64; k++) {
        float4 xa0 = *(const float4*)&x_s[k][tx * 8];
        float4 xa1 = *(const float4*)&x_s[k][tx * 8 + 4];
        ulonglong2 wA = *(const ulonglong2*)&w_s[k][gy * 8];
        ulonglong2 wB = *(const ulonglong2*)&w_s[k][gy * 8 + 4];
        float xv[8] = {xa0.x, xa0.y, xa0.z, xa0.w, xa1.x, xa1.y, xa1.z, xa1.w};
#pragma unroll
        for (int ti = 0; ti < 8; ti++) {
            unsigned long long xx = pack2(xv[ti], xv[ti]);
            acc2[ti][0] = ffma2(xx, wA.x, acc2[ti][0]);
            acc2[ti][1] = ffma2(xx, wA.y, acc2[ti][1]);
            acc2[ti][2] = ffma2(xx, wB.x, acc2[ti][2]);
            acc2[ti][3] = ffma2(xx, wB.y, acc2[ti][3]);
        }
    }

    const int g8 = gy * 8;
    float4 bv0 = *(const float4*)&b1[g8];
    float4 bv1 = *(const float4*)&b1[g8 + 4];
#pragma unroll
    for (int ti = 0; ti < 8; ti++) {
        int t = t0 + tx * 8 + ti;
        if (t >= TO) continue;
        float4 v0, v1;
        unpack2(acc2[ti][0], v0.x, v0.y);
        unpack2(acc2[ti][1], v0.z, v0.w);
        unpack2(acc2[ti][2], v1.x, v1.y);
        unpack2(acc2[ti][3], v1.z, v1.w);
        v0.x += bv0.x; v0.y += bv0.y; v0.z += bv0.z; v0.w += bv0.w;
        v1.x += bv1.x; v1.y += bv1.y; v1.z += bv1.z; v1.w += bv1.w;
        float* dst = &g_xz1[((size_t)b * TO + t) * G4 + g8];
        *(float4*)dst = v0;
        *(float4*)(dst + 4) = v1;
    }
}

// ---------------------------------------------------------------------------
// proj2 CHUNK kernel: xz2 rows [t_base+bx*32, +32) = h1 @ W2 + b2.
// 128 threads, 32t x 64g tile, 4t x 4g per thread, regs capped to 64 so one
// CTA CO-RESIDES with a scan CTA (53K + 8K regs) and eats its idle slots.
// smem ~40KB (under 48KB default).
// ---------------------------------------------------------------------------
#define PXPAD 36
__global__ void __launch_bounds__(128, 8)
proj2_chunk_kernel(const float* __restrict__ W2,
                   const float* __restrict__ b2,
                   int t_base) {
    extern __shared__ __align__(16) float sm[];
    float(*x_s)[PXPAD] = (float(*)[PXPAD])sm;               // [100][36]
    float(*w_s)[64]    = (float(*)[64])(sm + 100 * PXPAD);  // [100][64]

    const int b   = blockIdx.z;
    const int t0c = t_base + blockIdx.x * 32;
    const int g0  = blockIdx.y * 64;
    const int tid = threadIdx.x;

    // load h1 tile [32 t][100 k] transposed
    for (int i = tid; i < 32 * HID; i += 128) {
        int tt = i / HID, k = i % HID;
        int t = t0c + tt;
        x_s[k][tt] = (t < TO) ? g_h1[((size_t)b * TO + t) * HID + k] : 0.f;
    }
    for (int i = tid; i < HID * 64; i += 128) {
        int k = i >> 6, gg = i & 63;
        int g = g0 + gg;
        w_s[k][gg] = (g < G4) ? W2[k * G4 + g] : 0.f;
    }
    __syncthreads();

    const int gy = tid & 15;
    const int tx = tid >> 4;
    unsigned long long acc2[4][2] = {};
#pragma unroll 4
    for (int k = 0; k < HID; k++) {
        float4 xa = *(const float4*)&x_s[k][tx * 4];
        ulonglong2 wv2 = *(const ulonglong2*)&w_s[k][gy * 4];
        float xv[4] = {xa.x, xa.y, xa.z, xa.w};
#pragma unroll
        for (int ti = 0; ti < 4; ti++) {
            unsigned long long xx = pack2(xv[ti], xv[ti]);
            acc2[ti][0] = ffma2(xx, wv2.x, acc2[ti][0]);
            acc2[ti][1] = ffma2(xx, wv2.y, acc2[ti][1]);
        }
    }

    const int g4 = g0 + gy * 4;
    if (g4 < G4) {
        float4 bv = *(const float4*)&b2[g4];
#pragma unroll
        for (int ti = 0; ti < 4; ti++) {
            int t = t0c + tx * 4 + ti;
            if (t >= TO) continue;
            float4 v;
            unpack2(acc2[ti][0], v.x, v.y);
            unpack2(acc2[ti][1], v.z, v.w);
            v.x += bv.x; v.y += bv.y; v.z += bv.z; v.w += bv.w;
            *(float4*)&g_xz2[((size_t)b * TO + t) * G4 + g4] = v;
        }
    }
}

// ---------------------------------------------------------------------------
// Scan CHUNK kernel: exact R7 step body over t in [t0,t1), with h/c state
// carried through global buffers between chunks (bit-identical math).
// init=1: h,c start at zero. At chunk end, sub==0 writes state.
// ---------------------------------------------------------------------------
__global__ void __launch_bounds__(400, 1)
lstm_scan_chunk(const float* __restrict__ xz,
                const float* __restrict__ U,
                float* __restrict__ hseq,
                float* __restrict__ cstate,
                float* __restrict__ hstate,
                int t0, int t1, int seq, int init) {
    __shared__ __align__(16) float h_s[2][104];

    const int b = blockIdx.x;
    const int tid = threadIdx.x;
    const int j   = tid >> 2;
    const int sub = tid & 3;
    const int g   = sub * 100 + j;          // column in z-space
    const int lane = tid & 31;
    const unsigned mask = (tid < 384) ? 0xFFFFFFFFu : 0x0000FFFFu;

    // U column packed in k-pairs: Ur2[k2] = (U[2k2, g], U[2k2+1, g])
    unsigned long long Ur2[50];
#pragma unroll
    for (int k2 = 0; k2 < 50; k2++)
        Ur2[k2] = pack2(U[(2 * k2) * G4 + g], U[(2 * k2 + 1) * G4 + g]);

    float c;
    if (init) {
        c = 0.f;
        if (tid < 104) { h_s[0][tid] = 0.f; h_s[1][tid] = 0.f; }
    } else {
        c = cstate[b * HID + j];
        if (tid < 104) {
            h_s[0][tid] = (tid < HID) ? hstate[b * HID + tid] : 0.f;
            h_s[1][tid] = 0.f;
        }
    }
    __syncthreads();

    const float* xzb = xz + (size_t)b * TO * G4;
    float xz_cur = xzb[(size_t)t0 * G4 + g];
    int cur = 0;
    float h = 0.f;

    for (int t = t0; t < t1; t++) {
        // prefetch next step's xz (full-step latency cover)
        float xz_nxt = 0.f;
        if (t + 1 < t1) xz_nxt = xzb[(size_t)(t + 1) * G4 + g];

        const ulonglong2* hp = (const ulonglong2*)h_s[cur];
        unsigned long long aA = 0ULL;   // packed (k%4==0 sum, k%4==1 sum)
        unsigned long long aB = 0ULL;   // packed (k%4==2 sum, k%4==3 sum)
#pragma unroll
        for (int k2 = 0; k2 < 25; k2++) {
            ulonglong2 hv = hp[k2];     // 4 h values (16B)
            aA = ffma2(hv.x, Ur2[2 * k2],     aA);
            aB = ffma2(hv.y, Ur2[2 * k2 + 1], aB);
        }
        float a0, a1, a2, a3;
        unpack2(aA, a0, a1);
        unpack2(aB, a2, a3);
        float z = (a0 + a1) + (a2 + a3) + xz_cur;

        // per-lane activation, then nibble gather of activated gate values
        float sg = 1.f / (1.f + __expf(-z));
        float act = (sub == 2) ? fmaxf(z, 0.f) : sg;
        const int base = lane & ~3;
        float ig = __shfl_sync(mask, act, base + 0);
        float fg = __shfl_sync(mask, act, base + 1);
        float gc = __shfl_sync(mask, act, base + 2);
        float og = __shfl_sync(mask, act, base + 3);

        c = fmaf(fg, c, ig * gc);
        h = og * fmaxf(c, 0.f);

        if (sub == 0) {
            h_s[cur ^ 1][j] = h;
            if (seq) hseq[((size_t)b * TO + t) * HID + j] = h;
        }
        __syncthreads();   // h published; all reads of h_s[cur] complete
        cur ^= 1;
        xz_cur = xz_nxt;
    }

    // carry state to next chunk (deterministic: all subs hold identical c,h)
    if (sub == 0) {
        cstate[b * HID + j] = c;
        hstate[b * HID + j] = h;
    }
}

// ---------------------------------------------------------------------------
// Kernel E: dense + softmax. One warp per batch row. Reads g_h2 (scan2 state).
// ---------------------------------------------------------------------------
__global__ void dense_softmax_kernel(const float* __restrict__ dw,
                                     const float* __restrict__ db,
                                     float* __restrict__ out) {
    const int b = blockIdx.x;
    const int lane = threadIdx.x;
    float p0 = 0.f, p1 = 0.f, p2 = 0.f;
    for (int j = lane; j < HID; j += 32) {
        float h = g_h2[b * HID + j];
        p0 = fmaf(h, dw[j * 3 + 0], p0);
        p1 = fmaf(h, dw[j * 3 + 1], p1);
        p2 = fmaf(h, dw[j * 3 + 2], p2);
    }
#pragma unroll
    for (int o = 16; o; o >>= 1) {
        p0 += __shfl_down_sync(0xffffffffu, p0, o);
        p1 += __shfl_down_sync(0xffffffffu, p1, o);
        p2 += __shfl_down_sync(0xffffffffu, p2, o);
    }
    if (lane == 0) {
        float l0 = p0 + db[0], l1 = p1 + db[1], l2 = p2 + db[2];
        float m = fmaxf(l0, fmaxf(l1, l2));
        float e0 = __expf(l0 - m), e1 = __expf(l1 - m), e2 = __expf(l2 - m);
        float inv = 1.f / (e0 + e1 + e2);
        out[b * 3 + 0] = e0 * inv;
        out[b * 3 + 1] = e1 * inv;
        out[b * 3 + 2] = e2 * inv;
    }
}

// ---------------------------------------------------------------------------
// Launch: scan1 chunked on the main (capture) stream; each chunk signals an
// event that releases the matching proj2 chunk on a side stream. scan2 waits
// for the side stream to drain, then runs whole. Streams/events are created
// once on the first (uncaptured) call; during capture only launches/record/
// wait are issued (standard fork-join capture pattern).
// ---------------------------------------------------------------------------
extern "C" void kernel_launch(void* const* d_in, const int* in_sizes, int n_in,
                              void* d_out, int out_size) {
    const float* s       = (const float*)d_in[0];   // [128,2048,1]
    const float* conv_w  = (const float*)d_in[1];   // [2,1,64]
    const float* conv_b  = (const float*)d_in[2];   // [64]
    const float* lstm1_w = (const float*)d_in[3];   // [64,400]
    const float* lstm1_u = (const float*)d_in[4];   // [100,400]
    const float* lstm1_b = (const float*)d_in[5];   // [400]
    const float* lstm2_w = (const float*)d_in[6];   // [100,400]
    const float* lstm2_u = (const float*)d_in[7];   // [100,400]
    const float* lstm2_b = (const float*)d_in[8];   // [400]
    const float* dense_w = (const float*)d_in[9];   // [100,3]
    const float* dense_b = (const float*)d_in[10];  // [3]
    float* out = (float*)d_out;                     // [128,3]

    static bool s_init = false;
    static cudaStream_t sB;
    static cudaEvent_t evS1[NCHUNK];
    static cudaEvent_t evJoin;
    if (!s_init) {
        cudaStreamCreateWithFlags(&sB, cudaStreamNonBlocking);
        for (int i = 0; i < NCHUNK; i++)
            cudaEventCreateWithFlags(&evS1[i], cudaEventDisableTiming);
        cudaEventCreateWithFlags(&evJoin, cudaEventDisableTiming);
        s_init = true;
    }

    void* p_xz1; cudaGetSymbolAddress(&p_xz1, g_xz1);
    void* p_h1;  cudaGetSymbolAddress(&p_h1,  g_h1);
    void* p_xz2; cudaGetSymbolAddress(&p_xz2, g_xz2);
    void* p_c1;  cudaGetSymbolAddress(&p_c1,  g_c1);
    void* p_hs1; cudaGetSymbolAddress(&p_hs1, g_hs1);
    void* p_c2;  cudaGetSymbolAddress(&p_c2,  g_c2);
    void* p_h2;  cudaGetSymbolAddress(&p_h2,  g_h2);

    // Phase A: conv + input projection for LSTM1 (full-width 8x8 tile)
    {
        int smem = (68 + 64 * 64 + 64 * G4) * sizeof(float);  // ~119 KB
        cudaFuncSetAttribute(conv_xz1_kernel,
                             cudaFuncAttributeMaxDynamicSharedMemorySize, smem);
        dim3 grid(32, 1, BATCH);
        conv_xz1_kernel<<<grid, 400, smem>>>(s, conv_w, conv_b, lstm1_w, lstm1_b);
    }

    // Phase B+C pipelined: scan1 chunks (main stream), proj2 chunks (sB)
    const int p2smem = (100 * PXPAD + 100 * 64) * sizeof(float);  // ~40 KB
    for (int i = 0; i < NCHUNK; i++) {
        int t0 = i * CHUNK;
        int t1 = (t0 + CHUNK < TO) ? (t0 + CHUNK) : TO;
        lstm_scan_chunk<<<BATCH, 400>>>((const float*)p_xz1, lstm1_u,
                                        (float*)p_h1,
                                        (float*)p_c1, (float*)p_hs1,
                                        t0, t1, 1, (i == 0) ? 1 : 0);
        cudaEventRecord(evS1[i], 0);
        cudaStreamWaitEvent(sB, evS1[i], 0);
        dim3 pgrid(8, 7, BATCH);   // 8 t-tiles of 32, 7 g-tiles of 64
        proj2_chunk_kernel<<<pgrid, 128, p2smem, sB>>>(lstm2_w, lstm2_b, t0);
    }
    cudaEventRecord(evJoin, sB);
    cudaStreamWaitEvent(0, evJoin, 0);

    // Phase D: LSTM2 scan (whole range, single chunk; final h -> g_h2)
    lstm_scan_chunk<<<BATCH, 400>>>((const float*)p_xz2, lstm2_u,
                                    (float*)p_h1 /*unused*/,
                                    (float*)p_c2, (float*)p_h2,
                                    0, TO, 0, 1);
    // Phase E: dense + softmax
    dense_softmax_kernel<<<BATCH, 32>>>(dense_w, dense_b, out);
}